// round 4
// baseline (speedup 1.0000x reference)
#include <cuda_runtime.h>

// Problem constants
#define DIN   400
#define DOUT  100
#define NQ    10
#define NT    128          // threads per CTA (4 full warps)
#define CHUNK 50           // K-chunk of W staged in smem
#define NCHUNK (DIN / CHUNK)
#define WPAD  101          // 50x101 W tile, conflict-free
#define XPAD  12           // padded X row (16B aligned rows)
#define APAD  11           // padded A row (stride 11 -> conflict-free column access)

__device__ __forceinline__ float warp_sum(float x) {
    x += __shfl_down_sync(0xffffffffu, x, 16);
    x += __shfl_down_sync(0xffffffffu, x, 8);
    x += __shfl_down_sync(0xffffffffu, x, 4);
    x += __shfl_down_sync(0xffffffffu, x, 2);
    x += __shfl_down_sync(0xffffffffu, x, 1);
    return x;
}

__global__ __launch_bounds__(NT) void frmap_qr_kernel(
    const float* __restrict__ X,   // (B, DIN, NQ)
    const float* __restrict__ W,   // (DOUT, DIN)
    float* __restrict__ out)       // (B, DOUT, NQ)
{
    __shared__ float Xs[DIN * XPAD];      // 4800 f
    __shared__ float Ws[CHUNK * WPAD];    // 5050 f
    __shared__ float As[DOUT * APAD];     // 1100 f  (A matrix for QR)
    __shared__ float Vs[NQ * DOUT];       // 1000 f  (Householder vectors)
    __shared__ float tau_sh[NQ];
    __shared__ float red[NQ];             // reduction results
    __shared__ float wscr[4 * NQ];        // per-warp partials
    __shared__ float alpha_sh;

    const int tid  = threadIdx.x;
    const int b    = blockIdx.x;
    const int lane = tid & 31;
    const int wrp  = tid >> 5;

    // ---- load X[b] into padded smem (coalesced) ----
    const float* Xb = X + (long long)b * (DIN * NQ);
    for (int l = tid; l < DIN * NQ; l += NT) {
        int i = l / NQ;
        int q = l - i * NQ;
        Xs[i * XPAD + q] = Xb[l];
    }

    // ---- GEMM: thread tid (<100) computes row o=tid of Y = W @ X[b] ----
    float acc[NQ];
    #pragma unroll
    for (int k = 0; k < NQ; k++) acc[k] = 0.f;

    for (int c = 0; c < NCHUNK; c++) {
        const int i0 = c * CHUNK;
        __syncthreads();                      // Ws reuse / Xs visibility
        for (int l = tid; l < CHUNK * DOUT; l += NT) {
            int oo = l / CHUNK;               // output row
            int ii = l - oo * CHUNK;          // k within chunk
            Ws[ii * WPAD + oo] = W[oo * DIN + i0 + ii];   // coalesced read, conflict-free write
        }
        __syncthreads();
        if (tid < DOUT) {
            #pragma unroll 2
            for (int ii = 0; ii < CHUNK; ii++) {
                float wv = Ws[ii * WPAD + tid];           // stride-1 across threads
                const float* xr = &Xs[(i0 + ii) * XPAD];  // 16B aligned
                float4 x0 = *(const float4*)(xr);
                float4 x1 = *(const float4*)(xr + 4);
                float2 x2 = *(const float2*)(xr + 8);
                acc[0] += wv * x0.x; acc[1] += wv * x0.y;
                acc[2] += wv * x0.z; acc[3] += wv * x0.w;
                acc[4] += wv * x1.x; acc[5] += wv * x1.y;
                acc[6] += wv * x1.z; acc[7] += wv * x1.w;
                acc[8] += wv * x2.x; acc[9] += wv * x2.y;
            }
        }
    }

    // ---- stage A (=Y) into smem for QR ----
    if (tid < DOUT) {
        #pragma unroll
        for (int k = 0; k < NQ; k++) As[tid * APAD + k] = acc[k];
    }
    __syncthreads();

    // ---- Householder QR (LAPACK slarfg convention) ----
    #pragma unroll 1
    for (int j = 0; j < NQ; j++) {
        float ajv = 0.f;
        if (tid < DOUT) ajv = As[tid * APAD + j];
        if (tid == j) alpha_sh = ajv;
        float val = (tid < DOUT && tid > j) ? ajv * ajv : 0.f;
        val = warp_sum(val);
        if (lane == 0) wscr[wrp] = val;
        __syncthreads();
        float xnorm2 = wscr[0] + wscr[1] + wscr[2] + wscr[3];
        float alpha  = alpha_sh;

        float tau, inv_amb;
        if (xnorm2 <= 0.f) {
            tau = 0.f; inv_amb = 0.f;
        } else {
            float nrm  = sqrtf(alpha * alpha + xnorm2);
            float beta = (alpha >= 0.f) ? -nrm : nrm;   // beta = -sign(alpha)*||x||
            tau     = (beta - alpha) / beta;
            inv_amb = 1.f / (alpha - beta);
        }
        if (tid == 0) tau_sh[j] = tau;

        float v = 0.f;
        if (tid < DOUT) {
            if (tid == j)      v = 1.f;
            else if (tid > j)  v = ajv * inv_amb;
            Vs[j * DOUT + tid] = v;
        }

        // d_k = v . A[:,k], batched over the 10 columns
        float vals[NQ];
        if (tid < DOUT) {
            #pragma unroll
            for (int k = 0; k < NQ; k++) vals[k] = v * As[tid * APAD + k];
        } else {
            #pragma unroll
            for (int k = 0; k < NQ; k++) vals[k] = 0.f;
        }
        #pragma unroll
        for (int k = 0; k < NQ; k++) vals[k] = warp_sum(vals[k]);
        __syncthreads();                       // xnorm2 readers done before wscr reuse
        if (lane == 0) {
            #pragma unroll
            for (int k = 0; k < NQ; k++) wscr[wrp * NQ + k] = vals[k];
        }
        __syncthreads();
        if (tid < NQ)
            red[tid] = wscr[tid] + wscr[NQ + tid] + wscr[2 * NQ + tid] + wscr[3 * NQ + tid];
        __syncthreads();

        // A[:,k] -= v * (tau * d_k) for trailing columns
        if (tid < DOUT) {
            #pragma unroll
            for (int k = 0; k < NQ; k++) {
                if (k > j) As[tid * APAD + k] -= v * (tau * red[k]);
            }
        }
        __syncthreads();
    }

    // ---- orgqr: Q = H_0 ... H_9 * I(:, 0:10), backward accumulation ----
    float qrow[NQ];
    #pragma unroll
    for (int k = 0; k < NQ; k++) qrow[k] = (tid == k) ? 1.f : 0.f;

    #pragma unroll 1
    for (int j = NQ - 1; j >= 0; j--) {
        float v = (tid < DOUT) ? Vs[j * DOUT + tid] : 0.f;
        float vals[NQ];
        #pragma unroll
        for (int k = 0; k < NQ; k++) vals[k] = v * qrow[k];
        #pragma unroll
        for (int k = 0; k < NQ; k++) vals[k] = warp_sum(vals[k]);
        __syncthreads();                       // previous red readers done
        if (lane == 0) {
            #pragma unroll
            for (int k = 0; k < NQ; k++) wscr[wrp * NQ + k] = vals[k];
        }
        __syncthreads();
        if (tid < NQ)
            red[tid] = wscr[tid] + wscr[NQ + tid] + wscr[2 * NQ + tid] + wscr[3 * NQ + tid];
        __syncthreads();
        float tj = tau_sh[j];
        #pragma unroll
        for (int k = 0; k < NQ; k++) qrow[k] -= v * (tj * red[k]);
    }

    // ---- write Q row ----
    if (tid < DOUT) {
        float* po = out + (long long)b * (DOUT * NQ) + tid * NQ;
        #pragma unroll
        for (int k = 0; k < NQ; k++) po[k] = qrow[k];
    }
}

extern "C" void kernel_launch(void* const* d_in, const int* in_sizes, int n_in,
                              void* d_out, int out_size)
{
    const float* X = (const float*)d_in[0];
    const float* W = (const float*)d_in[1];
    // defensive: detect swapped input order by size signature
    if (n_in >= 2 && in_sizes[0] == DOUT * DIN && in_sizes[1] != DOUT * DIN) {
        const float* t = X; X = W; W = t;
    }
    int batches = out_size / (DOUT * NQ);
    frmap_qr_kernel<<<batches, NT>>>(X, W, (float*)d_out);
}

// round 6
// speedup vs baseline: 2.0060x; 2.0060x over previous
#include <cuda_runtime.h>

#define DIN   400
#define DOUT  100
#define NQ    10
#define NT    128
#define NKK   (DIN / 4)      // 100 float4 k-groups
#define XPAD  12             // padded X row, 16B-aligned rows
#define APAD  11             // odd stride -> conflict-free strided column access

// W transposed+packed: Wt4[kk*DOUT + o] = {W[o,4kk], W[o,4kk+1], W[o,4kk+2], W[o,4kk+3]}
__device__ float4 g_Wt4[NKK * DOUT];

__global__ void transpose_w_kernel(const float* __restrict__ W) {
    int idx = blockIdx.x * blockDim.x + threadIdx.x;
    if (idx < NKK * DOUT) {
        int kk = idx / DOUT;
        int o  = idx - kk * DOUT;
        g_Wt4[idx] = *(const float4*)(W + o * DIN + kk * 4);
    }
}

__device__ __forceinline__ float xor_sum(float x) {
    x += __shfl_xor_sync(0xffffffffu, x, 16);
    x += __shfl_xor_sync(0xffffffffu, x, 8);
    x += __shfl_xor_sync(0xffffffffu, x, 4);
    x += __shfl_xor_sync(0xffffffffu, x, 2);
    x += __shfl_xor_sync(0xffffffffu, x, 1);
    return x;
}

__global__ __launch_bounds__(NT) void frmap_qr_kernel(
    const float* __restrict__ X,   // (B, DIN, NQ)
    float* __restrict__ out)       // (B, DOUT, NQ)
{
    __shared__ __align__(16) float Xs[DIN * XPAD];   // 19.2 KB; reused as Qs after GEMM
    __shared__ float As[DOUT * APAD];                // 4.4 KB
    __shared__ float Vs[NQ * DOUT];                  // 4.0 KB
    __shared__ float tau_sh[NQ];

    const int tid  = threadIdx.x;
    const int b    = blockIdx.x;
    const int lane = tid & 31;
    const int wrp  = tid >> 5;

    // ---- load X[b] into padded smem (vectorized: rows of 10 never straddle a float2) ----
    {
        const float2* Xb2 = (const float2*)(X + (long long)b * (DIN * NQ));
        for (int m = tid; m < (DIN * NQ) / 2; m += NT) {
            float2 v = Xb2[m];
            int f = 2 * m;
            int i = f / 10;
            int q = f - i * 10;
            Xs[i * XPAD + q]     = v.x;
            Xs[i * XPAD + q + 1] = v.y;
        }
    }
    __syncthreads();

    // ---- GEMM: thread o (<100) computes row o of Y = W @ X[b] ----
    if (tid < DOUT) {
        const int o = tid;
        float acc[NQ];
        #pragma unroll
        for (int k = 0; k < NQ; k++) acc[k] = 0.f;

        #pragma unroll 2
        for (int kk = 0; kk < NKK; kk++) {
            float4 w = g_Wt4[kk * DOUT + o];   // coalesced, L2-resident
            float wv[4] = {w.x, w.y, w.z, w.w};
            #pragma unroll
            for (int s = 0; s < 4; s++) {
                const float* xr = &Xs[(4 * kk + s) * XPAD];
                float4 x0 = *(const float4*)(xr);
                float4 x1 = *(const float4*)(xr + 4);
                float2 x2 = *(const float2*)(xr + 8);
                acc[0] += wv[s] * x0.x; acc[1] += wv[s] * x0.y;
                acc[2] += wv[s] * x0.z; acc[3] += wv[s] * x0.w;
                acc[4] += wv[s] * x1.x; acc[5] += wv[s] * x1.y;
                acc[6] += wv[s] * x1.z; acc[7] += wv[s] * x1.w;
                acc[8] += wv[s] * x2.x; acc[9] += wv[s] * x2.y;
            }
        }
        #pragma unroll
        for (int k = 0; k < NQ; k++) As[o * APAD + k] = acc[k];
    }
    __syncthreads();

    // ---- QR by warp 0 only: barrier-free (shfl_xor reductions, rows lane+32r) ----
    if (wrp == 0) {
        // Householder, LAPACK slarfg convention
        #pragma unroll 1
        for (int j = 0; j < NQ; j++) {
            float aj[4];
            #pragma unroll
            for (int r = 0; r < 4; r++) {
                int row = lane + 32 * r;
                aj[r] = (row < DOUT) ? As[row * APAD + j] : 0.f;
            }
            float alpha = __shfl_sync(0xffffffffu, aj[0], j);   // row j lives at lane j, r=0
            float s = 0.f;
            #pragma unroll
            for (int r = 0; r < 4; r++) {
                int row = lane + 32 * r;
                if (row < DOUT && row > j) s += aj[r] * aj[r];
            }
            s = xor_sum(s);

            float tau, inv_amb;
            if (s <= 0.f) {
                tau = 0.f; inv_amb = 0.f;
            } else {
                float nrm  = sqrtf(alpha * alpha + s);
                float beta = (alpha >= 0.f) ? -nrm : nrm;   // beta = -sign(alpha)*||x||
                tau     = (beta - alpha) / beta;
                inv_amb = 1.f / (alpha - beta);
            }
            if (lane == 0) tau_sh[j] = tau;

            float v[4];
            #pragma unroll
            for (int r = 0; r < 4; r++) {
                int row = lane + 32 * r;
                float vv = 0.f;
                if (row == j)                    vv = 1.f;
                else if (row > j && row < DOUT)  vv = aj[r] * inv_amb;
                v[r] = vv;
                if (row < DOUT) Vs[j * DOUT + row] = vv;
            }

            // trailing update: A[:,k] -= v * tau * (v . A[:,k]) for k > j
            #pragma unroll
            for (int k = 0; k < NQ; k++) {
                if (k > j) {                       // uniform branch across warp
                    float d = 0.f;
                    #pragma unroll
                    for (int r = 0; r < 4; r++) {
                        int row = lane + 32 * r;
                        if (row < DOUT) d += v[r] * As[row * APAD + k];
                    }
                    d = xor_sum(d);
                    float c = tau * d;
                    #pragma unroll
                    for (int r = 0; r < 4; r++) {
                        int row = lane + 32 * r;
                        if (row < DOUT) As[row * APAD + k] -= v[r] * c;
                    }
                }
            }
        }

        // orgqr: Q = H_0..H_9 * I(:,0:10), backward accumulation, in registers
        float q[4][NQ];
        #pragma unroll
        for (int r = 0; r < 4; r++) {
            int row = lane + 32 * r;
            #pragma unroll
            for (int k = 0; k < NQ; k++) q[r][k] = (row == k) ? 1.f : 0.f;
        }

        #pragma unroll 1
        for (int j = NQ - 1; j >= 0; j--) {
            float v[4];
            #pragma unroll
            for (int r = 0; r < 4; r++) {
                int row = lane + 32 * r;
                v[r] = (row < DOUT) ? Vs[j * DOUT + row] : 0.f;
            }
            float tj = tau_sh[j];
            #pragma unroll
            for (int k = 0; k < NQ; k++) {
                if (k >= j) {                      // columns k<j are still e_k; untouched
                    float d = 0.f;
                    #pragma unroll
                    for (int r = 0; r < 4; r++) d += v[r] * q[r][k];
                    d = xor_sum(d);
                    float c = tj * d;
                    #pragma unroll
                    for (int r = 0; r < 4; r++) q[r][k] -= v[r] * c;
                }
            }
        }

        // stage Q into smem (reuse Xs region) for a coalesced vector write
        float* Qs = Xs;
        #pragma unroll
        for (int r = 0; r < 4; r++) {
            int row = lane + 32 * r;
            if (row < DOUT) {
                #pragma unroll
                for (int k = 0; k < NQ; k++) Qs[row * NQ + k] = q[r][k];
            }
        }
    }
    __syncthreads();

    // ---- coalesced float4 write-out (1000 floats = 250 float4) ----
    {
        const float4* Qs4 = (const float4*)Xs;
        float4* out4 = (float4*)(out + (long long)b * (DOUT * NQ));
        for (int m = tid; m < (DOUT * NQ) / 4; m += NT) out4[m] = Qs4[m];
    }
}

extern "C" void kernel_launch(void* const* d_in, const int* in_sizes, int n_in,
                              void* d_out, int out_size)
{
    const float* X = (const float*)d_in[0];
    const float* W = (const float*)d_in[1];
    if (n_in >= 2 && in_sizes[0] == DOUT * DIN && in_sizes[1] != DOUT * DIN) {
        const float* t = X; X = W; W = t;
    }
    transpose_w_kernel<<<(NKK * DOUT + 255) / 256, 256>>>(W);
    int batches = out_size / (DOUT * NQ);
    frmap_qr_kernel<<<batches, NT>>>(X, (float*)d_out);
}

// round 7
// speedup vs baseline: 2.0889x; 1.0413x over previous
#include <cuda_runtime.h>

#define DIN   400
#define DOUT  100
#define NQ    10
#define NT    128
#define NKK   (DIN / 4)      // 100 float4 k-groups
#define XPAD  12             // padded X row, 16B-aligned rows
#define APAD  11             // odd stride -> conflict-free strided column access

// W transposed+packed: Wt4[kk*DOUT + o] = {W[o,4kk], W[o,4kk+1], W[o,4kk+2], W[o,4kk+3]}
__device__ float4 g_Wt4[NKK * DOUT];

__global__ void transpose_w_kernel(const float* __restrict__ W) {
    int idx = blockIdx.x * blockDim.x + threadIdx.x;
    if (idx < NKK * DOUT) {
        int kk = idx / DOUT;
        int o  = idx - kk * DOUT;
        g_Wt4[idx] = *(const float4*)(W + o * DIN + kk * 4);
    }
}

__device__ __forceinline__ float xor_sum(float x) {
    x += __shfl_xor_sync(0xffffffffu, x, 16);
    x += __shfl_xor_sync(0xffffffffu, x, 8);
    x += __shfl_xor_sync(0xffffffffu, x, 4);
    x += __shfl_xor_sync(0xffffffffu, x, 2);
    x += __shfl_xor_sync(0xffffffffu, x, 1);
    return x;
}

// ---- packed f32x2 helpers (FFMA2: PTX-only, ptxas never emits from C++) ----
__device__ __forceinline__ unsigned long long pack2(float x) {
    unsigned long long r;
    asm("mov.b64 %0, {%1, %1};" : "=l"(r) : "f"(x));
    return r;
}
__device__ __forceinline__ void fma2(unsigned long long& d,
                                     unsigned long long a,
                                     unsigned long long b) {
    asm("fma.rn.f32x2 %0, %1, %2, %0;" : "+l"(d) : "l"(a), "l"(b));
}
__device__ __forceinline__ void unpack2(unsigned long long v, float& lo, float& hi) {
    asm("mov.b64 {%0, %1}, %2;" : "=f"(lo), "=f"(hi) : "l"(v));
}

__global__ __launch_bounds__(NT) void frmap_qr_kernel(
    const float* __restrict__ X,   // (B, DIN, NQ)
    float* __restrict__ out)       // (B, DOUT, NQ)
{
    __shared__ __align__(16) float Xs[DIN * XPAD];   // 19.2 KB; reused as Qs after GEMM
    __shared__ float As[DOUT * APAD];                // 4.4 KB
    __shared__ float Vs[NQ * DOUT];                  // 4.0 KB
    __shared__ float tau_sh[NQ];

    const int tid  = threadIdx.x;
    const int b    = blockIdx.x;
    const int lane = tid & 31;
    const int wrp  = tid >> 5;
    const int qw   = b & 3;        // rotate QR warp across SMSPs per block

    // ---- load X[b] into padded smem (vectorized: rows of 10 never straddle a float2) ----
    {
        const float2* Xb2 = (const float2*)(X + (long long)b * (DIN * NQ));
        for (int m = tid; m < (DIN * NQ) / 2; m += NT) {
            float2 v = Xb2[m];
            int f = 2 * m;
            int i = f / 10;
            int q = f - i * 10;
            Xs[i * XPAD + q]     = v.x;
            Xs[i * XPAD + q + 1] = v.y;
        }
    }
    __syncthreads();

    // ---- GEMM: thread o (<100) computes row o of Y = W @ X[b], f32x2-packed ----
    if (tid < DOUT) {
        const int o = tid;
        unsigned long long acc[5];
        #pragma unroll
        for (int p = 0; p < 5; p++) acc[p] = 0ull;   // {0.f, 0.f}

        #pragma unroll 2
        for (int kk = 0; kk < NKK; kk++) {
            float4 w = g_Wt4[kk * DOUT + o];   // coalesced, L2-resident
            unsigned long long wp[4];
            wp[0] = pack2(w.x); wp[1] = pack2(w.y);
            wp[2] = pack2(w.z); wp[3] = pack2(w.w);
            #pragma unroll
            for (int s = 0; s < 4; s++) {
                const float* xr = &Xs[(4 * kk + s) * XPAD];  // 16B-aligned row
                ulonglong2 x01 = *(const ulonglong2*)(xr);       // q-pairs 0,1
                ulonglong2 x23 = *(const ulonglong2*)(xr + 4);   // q-pairs 2,3
                unsigned long long x4 = *(const unsigned long long*)(xr + 8); // pair 4
                fma2(acc[0], wp[s], x01.x);
                fma2(acc[1], wp[s], x01.y);
                fma2(acc[2], wp[s], x23.x);
                fma2(acc[3], wp[s], x23.y);
                fma2(acc[4], wp[s], x4);
            }
        }
        #pragma unroll
        for (int p = 0; p < 5; p++) {
            float lo, hi;
            unpack2(acc[p], lo, hi);
            As[o * APAD + 2 * p]     = lo;
            As[o * APAD + 2 * p + 1] = hi;
        }
    }
    __syncthreads();

    // ---- QR by one warp (rotated per block): barrier-free shfl_xor reductions ----
    if (wrp == qw) {
        // Householder, LAPACK slarfg convention
        #pragma unroll 1
        for (int j = 0; j < NQ; j++) {
            float aj[4];
            #pragma unroll
            for (int r = 0; r < 4; r++) {
                int row = lane + 32 * r;
                aj[r] = (row < DOUT) ? As[row * APAD + j] : 0.f;
            }
            float alpha = __shfl_sync(0xffffffffu, aj[0], j);   // row j: lane j, r=0
            float s = 0.f;
            #pragma unroll
            for (int r = 0; r < 4; r++) {
                int row = lane + 32 * r;
                if (row < DOUT && row > j) s += aj[r] * aj[r];
            }
            s = xor_sum(s);

            float tau, inv_amb;
            if (s <= 0.f) {
                tau = 0.f; inv_amb = 0.f;
            } else {
                float nrm  = sqrtf(alpha * alpha + s);
                float beta = (alpha >= 0.f) ? -nrm : nrm;   // beta = -sign(alpha)*||x||
                tau     = (beta - alpha) / beta;
                inv_amb = 1.f / (alpha - beta);
            }
            if (lane == 0) tau_sh[j] = tau;

            float v[4];
            #pragma unroll
            for (int r = 0; r < 4; r++) {
                int row = lane + 32 * r;
                float vv = 0.f;
                if (row == j)                    vv = 1.f;
                else if (row > j && row < DOUT)  vv = aj[r] * inv_amb;
                v[r] = vv;
                if (row < DOUT) Vs[j * DOUT + row] = vv;
            }

            // trailing update: A[:,k] -= v * tau * (v . A[:,k]) for k > j
            #pragma unroll
            for (int k = 0; k < NQ; k++) {
                if (k > j) {                       // uniform branch across warp
                    float d = 0.f;
                    #pragma unroll
                    for (int r = 0; r < 4; r++) {
                        int row = lane + 32 * r;
                        if (row < DOUT) d += v[r] * As[row * APAD + k];
                    }
                    d = xor_sum(d);
                    float c = tau * d;
                    #pragma unroll
                    for (int r = 0; r < 4; r++) {
                        int row = lane + 32 * r;
                        if (row < DOUT) As[row * APAD + k] -= v[r] * c;
                    }
                }
            }
        }

        // orgqr: Q = H_0..H_9 * I(:,0:10), backward accumulation, in registers
        float q[4][NQ];
        #pragma unroll
        for (int r = 0; r < 4; r++) {
            int row = lane + 32 * r;
            #pragma unroll
            for (int k = 0; k < NQ; k++) q[r][k] = (row == k) ? 1.f : 0.f;
        }

        #pragma unroll 1
        for (int j = NQ - 1; j >= 0; j--) {
            float v[4];
            #pragma unroll
            for (int r = 0; r < 4; r++) {
                int row = lane + 32 * r;
                v[r] = (row < DOUT) ? Vs[j * DOUT + row] : 0.f;
            }
            float tj = tau_sh[j];
            #pragma unroll
            for (int k = 0; k < NQ; k++) {
                if (k >= j) {                      // columns k<j are still e_k
                    float d = 0.f;
                    #pragma unroll
                    for (int r = 0; r < 4; r++) d += v[r] * q[r][k];
                    d = xor_sum(d);
                    float c = tj * d;
                    #pragma unroll
                    for (int r = 0; r < 4; r++) q[r][k] -= v[r] * c;
                }
            }
        }

        // stage Q into smem (reuse Xs region) for a coalesced vector write
        float* Qs = Xs;
        #pragma unroll
        for (int r = 0; r < 4; r++) {
            int row = lane + 32 * r;
            if (row < DOUT) {
                #pragma unroll
                for (int k = 0; k < NQ; k++) Qs[row * NQ + k] = q[r][k];
            }
        }
    }
    __syncthreads();

    // ---- coalesced float4 write-out (1000 floats = 250 float4) ----
    {
        const float4* Qs4 = (const float4*)Xs;
        float4* out4 = (float4*)(out + (long long)b * (DOUT * NQ));
        for (int m = tid; m < (DOUT * NQ) / 4; m += NT) out4[m] = Qs4[m];
    }
}

extern "C" void kernel_launch(void* const* d_in, const int* in_sizes, int n_in,
                              void* d_out, int out_size)
{
    const float* X = (const float*)d_in[0];
    const float* W = (const float*)d_in[1];
    if (n_in >= 2 && in_sizes[0] == DOUT * DIN && in_sizes[1] != DOUT * DIN) {
        const float* t = X; X = W; W = t;
    }
    transpose_w_kernel<<<(NKK * DOUT + 255) / 256, 256>>>(W);
    int batches = out_size / (DOUT * NQ);
    frmap_qr_kernel<<<batches, NT>>>(X, (float*)d_out);
}